// round 14
// baseline (speedup 1.0000x reference)
#include <cuda_runtime.h>
#include <cuda_bf16.h>
#include <mma.h>
#include <cstdint>
#include <math.h>

using namespace nvcuda;

#define BTCH 2
#define SEQ  2048
#define DIM  1024
#define NH   16
#define HDM  64
#define NTOK (BTCH*SEQ)

// ---------------- device global scratch (no allocs allowed) ----------------
__device__ __nv_bfloat16 g_i0h[NTOK*DIM], g_i0l[NTOK*DIM];
__device__ __nv_bfloat16 g_i1h[NTOK*DIM], g_i1l[NTOK*DIM];
__device__ __nv_bfloat16 g_i2h[NTOK*DIM], g_i2l[NTOK*DIM];
__device__ __nv_bfloat16 g_w0h[DIM*DIM], g_w0l[DIM*DIM];
__device__ __nv_bfloat16 g_w1h[DIM*DIM], g_w1l[DIM*DIM];
__device__ __nv_bfloat16 g_w2h[DIM*DIM], g_w2l[DIM*DIM];
__device__ __nv_bfloat16 g_w3h[DIM*DIM], g_w3l[DIM*DIM];
__device__ __nv_bfloat16 g_qh[NTOK*DIM], g_ql[NTOK*DIM];
__device__ __nv_bfloat16 g_kh[NTOK*DIM], g_kl[NTOK*DIM];
__device__ __nv_bfloat16 g_vh[NTOK*DIM], g_vl[NTOK*DIM];
__device__ __nv_bfloat16 g_ath[NTOK*DIM], g_atl[NTOK*DIM];

__device__ __forceinline__ uint2 pack4_bf16(float a, float b, float c, float d) {
    __nv_bfloat162 lo = __floats2bfloat162_rn(a, b);
    __nv_bfloat162 hi = __floats2bfloat162_rn(c, d);
    uint2 r;
    r.x = *reinterpret_cast<uint32_t*>(&lo);
    r.y = *reinterpret_cast<uint32_t*>(&hi);
    return r;
}

// FMA-pipe exp2: 2^x for x <= 0 (scores pre-scaled by log2(e)). ~1e-7 accuracy.
__device__ __forceinline__ float fast_exp2(float x) {
    x = fmaxf(x, -120.f);
    float z = x + 12582912.f;
    float fn = z - 12582912.f;
    float f = x - fn;                            // f in [-0.5, 0.5]
    int n = __float_as_int(z);
    float p = 0.0013333558f;
    p = fmaf(p, f, 0.0096181291f);
    p = fmaf(p, f, 0.0555041087f);
    p = fmaf(p, f, 0.2402264923f);
    p = fmaf(p, f, 0.6931471806f);
    p = fmaf(p, f, 1.0f);
    return __int_as_float(__float_as_int(p) + (n << 23));
}

__device__ __forceinline__ void cp16(uint32_t dst, const void* src) {
    asm volatile("cp.async.cg.shared.global [%0], [%1], 16;"
                 :: "r"(dst), "l"(src) : "memory");
}
__device__ __forceinline__ void cp_commit() {
    asm volatile("cp.async.commit_group;" ::: "memory");
}
__device__ __forceinline__ void cp_wait1() {
    asm volatile("cp.async.wait_group 1;" ::: "memory");
}
__device__ __forceinline__ void cp_wait0() {
    asm volatile("cp.async.wait_group 0;" ::: "memory");
}

__device__ __forceinline__ void mma16816(float* d, const uint32_t* a,
                                         const uint32_t* b, const float* c) {
    asm volatile("mma.sync.aligned.m16n8k16.row.col.f32.bf16.bf16.f32 "
        "{%0,%1,%2,%3}, {%4,%5,%6,%7}, {%8,%9}, {%10,%11,%12,%13};"
        : "=f"(d[0]),"=f"(d[1]),"=f"(d[2]),"=f"(d[3])
        : "r"(a[0]),"r"(a[1]),"r"(a[2]),"r"(a[3]), "r"(b[0]),"r"(b[1]),
          "f"(c[0]),"f"(c[1]),"f"(c[2]),"f"(c[3]));
}
__device__ __forceinline__ void ldsm4(uint32_t* r, uint32_t addr) {
    asm volatile("ldmatrix.sync.aligned.m8n8.x4.shared.b16 {%0,%1,%2,%3}, [%4];"
        : "=r"(r[0]),"=r"(r[1]),"=r"(r[2]),"=r"(r[3]) : "r"(addr));
}
__device__ __forceinline__ void ldsm4t(uint32_t* r, uint32_t addr) {
    asm volatile("ldmatrix.sync.aligned.m8n8.x4.trans.shared.b16 {%0,%1,%2,%3}, [%4];"
        : "=r"(r[0]),"=r"(r[1]),"=r"(r[2]),"=r"(r[3]) : "r"(addr));
}
__device__ __forceinline__ void split2(float x, float y, uint32_t& h, uint32_t& l) {
    __nv_bfloat162 hh = __floats2bfloat162_rn(x, y);
    float hx = __bfloat162float(hh.x), hy = __bfloat162float(hh.y);
    __nv_bfloat162 ll = __floats2bfloat162_rn(x - hx, y - hy);
    h = *reinterpret_cast<uint32_t*>(&hh);
    l = *reinterpret_cast<uint32_t*>(&ll);
}

// ---------------------------------------------------------------------------
// fp32 -> bf16 hi/lo split (activations + weights)
// ---------------------------------------------------------------------------
struct Split4 {
    const float* s[4];
    __nv_bfloat16* h[4];
    __nv_bfloat16* l[4];
};
__global__ void splitk(Split4 a) {
    int z = blockIdx.z;
    size_t i = ((size_t)blockIdx.x * blockDim.x + threadIdx.x) * 4;
    float4 v = *(const float4*)(a.s[z] + i);
    float hx = __bfloat162float(__float2bfloat16(v.x));
    float hy = __bfloat162float(__float2bfloat16(v.y));
    float hz = __bfloat162float(__float2bfloat16(v.z));
    float hw = __bfloat162float(__float2bfloat16(v.w));
    *(uint2*)(a.h[z] + i) = pack4_bf16(hx, hy, hz, hw);
    *(uint2*)(a.l[z] + i) = pack4_bf16(v.x - hx, v.y - hy, v.z - hz, v.w - hw);
}

// ---------------------------------------------------------------------------
// bf16 WMMA GEMM + bias, 3x comp, cp.async double buffer, interleaved MMAs.
// ---------------------------------------------------------------------------
struct GemmArgs {
    const __nv_bfloat16 *ah[3], *al[3], *wh[3], *wl[3];
    const float* bias[3];
    float* c[3];
    __nv_bfloat16 *ch[3], *cl[3];
    float scale[3];
};

#define STAGE_BYTES 41984
#define OFF_AL 12288
#define OFF_BH 24576
#define OFF_BL 33280
#define GEMM_SMEM (2*STAGE_BYTES + 8192)

__global__ __launch_bounds__(256, 2)
void gemm_bf3(GemmArgs g) {
    extern __shared__ __align__(16) char sm[];
    int z = blockIdx.z;
    const __nv_bfloat16* Ahg = g.ah[z];
    const __nv_bfloat16* Alg = g.al[z];
    const __nv_bfloat16* Whg = g.wh[z];
    const __nv_bfloat16* Wlg = g.wl[z];
    const float* bias = g.bias[z];

    int tid  = threadIdx.x;
    int warp = tid >> 5;
    int lane = tid & 31;
    int wm   = warp >> 1;
    int wn   = warp & 1;
    int m0 = blockIdx.y * 128;
    int n0 = blockIdx.x * 128;

    uint32_t sbase = (uint32_t)__cvta_generic_to_shared(sm);
    float* biasS = (float*)(sm + 2 * STAGE_BYTES);

    auto stage_load = [&](int st, int c) {
        uint32_t b = sbase + st * STAGE_BYTES;
        #pragma unroll
        for (int r = 0; r < 2; r++) {
            int id = r * 256 + tid;
            int row = id >> 2, c4 = id & 3;
            size_t off = (size_t)(m0 + row) * DIM + c * 32 + c4 * 8;
            cp16(b + row * 96 + c4 * 16, Ahg + off);
            cp16(b + OFF_AL + row * 96 + c4 * 16, Alg + off);
        }
        #pragma unroll
        for (int r = 0; r < 2; r++) {
            int id = r * 256 + tid;
            int row = id >> 4, c4 = id & 15;
            size_t off = (size_t)(c * 32 + row) * DIM + n0 + c4 * 8;
            cp16(b + OFF_BH + row * 272 + c4 * 16, Whg + off);
            cp16(b + OFF_BL + row * 272 + c4 * 16, Wlg + off);
        }
    };

    for (int i = tid; i < 16 * 128; i += 256)
        biasS[i] = bias[n0 + (i & 127)];

    stage_load(0, 0);
    cp_commit();
    __syncthreads();

    wmma::fragment<wmma::accumulator, 16, 16, 16, float> acc[2][4];
    #pragma unroll
    for (int mi = 0; mi < 2; mi++)
        #pragma unroll
        for (int ni = 0; ni < 4; ni++)
            wmma::load_matrix_sync(acc[mi][ni], biasS + wn * 64 + ni * 16,
                                   128, wmma::mem_row_major);

    for (int c = 0; c < 32; c++) {
        if (c < 31) {
            stage_load((c + 1) & 1, c + 1);
            cp_commit();
            cp_wait1();
        } else {
            cp_wait0();
        }
        __syncthreads();

        const char* sb = sm + (c & 1) * STAGE_BYTES;
        const __nv_bfloat16* sAh = (const __nv_bfloat16*)sb;
        const __nv_bfloat16* sAl = (const __nv_bfloat16*)(sb + OFF_AL);
        const __nv_bfloat16* sBh = (const __nv_bfloat16*)(sb + OFF_BH);
        const __nv_bfloat16* sBl = (const __nv_bfloat16*)(sb + OFF_BL);

        #pragma unroll
        for (int kk = 0; kk < 2; kk++) {
            wmma::fragment<wmma::matrix_a, 16, 16, 16, __nv_bfloat16, wmma::row_major> ah[2], al[2];
            #pragma unroll
            for (int mi = 0; mi < 2; mi++) {
                wmma::load_matrix_sync(ah[mi], sAh + (wm*32 + mi*16) * 48 + kk*16, 48);
                wmma::load_matrix_sync(al[mi], sAl + (wm*32 + mi*16) * 48 + kk*16, 48);
            }
            #pragma unroll
            for (int ni = 0; ni < 4; ni++) {
                wmma::fragment<wmma::matrix_b, 16, 16, 16, __nv_bfloat16, wmma::row_major> bh, bl;
                wmma::load_matrix_sync(bh, sBh + (kk*16) * 136 + wn*64 + ni*16, 136);
                wmma::load_matrix_sync(bl, sBl + (kk*16) * 136 + wn*64 + ni*16, 136);
                // interleave the two accumulators (dep distance 2)
                wmma::mma_sync(acc[0][ni], ah[0], bh, acc[0][ni]);
                wmma::mma_sync(acc[1][ni], ah[1], bh, acc[1][ni]);
                wmma::mma_sync(acc[0][ni], ah[0], bl, acc[0][ni]);
                wmma::mma_sync(acc[1][ni], ah[1], bl, acc[1][ni]);
                wmma::mma_sync(acc[0][ni], al[0], bh, acc[0][ni]);
                wmma::mma_sync(acc[1][ni], al[1], bh, acc[1][ni]);
            }
        }
        __syncthreads();
    }

    if (g.ch[z]) {
        __nv_bfloat16* CH = g.ch[z];
        __nv_bfloat16* CL = g.cl[z];
        float sc = g.scale[z];
        float* scr = (float*)(sm + 1024 * warp);
        #pragma unroll
        for (int mi = 0; mi < 2; mi++)
            #pragma unroll
            for (int ni = 0; ni < 4; ni++) {
                __syncwarp();
                wmma::store_matrix_sync(scr, acc[mi][ni], 16, wmma::mem_row_major);
                __syncwarp();
                float4 v0 = *(float4*)&scr[lane * 8];
                float4 v1 = *(float4*)&scr[lane * 8 + 4];
                v0.x *= sc; v0.y *= sc; v0.z *= sc; v0.w *= sc;
                v1.x *= sc; v1.y *= sc; v1.z *= sc; v1.w *= sc;
                uint32_t h0,l0u,h1,l1u,h2,l2u,h3,l3u;
                split2(v0.x, v0.y, h0, l0u);
                split2(v0.z, v0.w, h1, l1u);
                split2(v1.x, v1.y, h2, l2u);
                split2(v1.z, v1.w, h3, l3u);
                int row = m0 + wm*32 + mi*16 + (lane >> 1);
                int col = n0 + wn*64 + ni*16 + (lane & 1) * 8;
                size_t go = (size_t)row * DIM + col;
                uint4 uh = make_uint4(h0, h1, h2, h3);
                uint4 ul = make_uint4(l0u, l1u, l2u, l3u);
                *(uint4*)&CH[go] = uh;
                *(uint4*)&CL[go] = ul;
            }
    } else {
        float* C = g.c[z];
        #pragma unroll
        for (int mi = 0; mi < 2; mi++)
            #pragma unroll
            for (int ni = 0; ni < 4; ni++)
                wmma::store_matrix_sync(
                    C + (size_t)(m0 + wm*32 + mi*16) * DIM + n0 + wn*64 + ni*16,
                    acc[mi][ni], DIM, wmma::mem_row_major);
    }
}

// ---------------------------------------------------------------------------
// FlashAttention-2 style mma.sync bf16 flash with hi/lo compensation.
// Prefetched ldmatrix fragments + interleaved accumulator chains + exp2.
// ---------------------------------------------------------------------------
#define QT 128
#define KT 64
#define LDT 72
#define TILE_E (KT*LDT)
#define STAGE_E (4*TILE_E)
#define FLASH_SMEM (2*STAGE_E*2)

__global__ __launch_bounds__(256, 2)
void flash_mma(const __nv_bfloat16* __restrict__ Qh_g, const __nv_bfloat16* __restrict__ Ql_g,
               const __nv_bfloat16* __restrict__ Kh_g, const __nv_bfloat16* __restrict__ Kl_g,
               const __nv_bfloat16* __restrict__ Vh_g, const __nv_bfloat16* __restrict__ Vl_g,
               __nv_bfloat16* __restrict__ Oh_g, __nv_bfloat16* __restrict__ Ol_g) {
    extern __shared__ __align__(16) char sm[];
    __nv_bfloat16* smb = (__nv_bfloat16*)sm;
    uint32_t sb = (uint32_t)__cvta_generic_to_shared(sm);

    int tid = threadIdx.x, lane = tid & 31, warp = tid >> 5;
    int bh = blockIdx.y, b = bh >> 4, h = bh & 15;
    int q0 = blockIdx.x * QT;

    auto stage_load = [&](int st, int t) {
        uint32_t base = sb + st * STAGE_E * 2;
        #pragma unroll
        for (int it2 = 0; it2 < 2; it2++) {
            int rem = it2 * 256 + tid;
            int r = rem >> 3, c8 = rem & 7;
            size_t gg = (size_t)(b*SEQ + t*KT + r) * DIM + h*HDM + c8*8;
            uint32_t so = (uint32_t)(r*LDT + c8*8) * 2;
            cp16(base + 0*TILE_E*2 + so, Kh_g + gg);
            cp16(base + 1*TILE_E*2 + so, Kl_g + gg);
            cp16(base + 2*TILE_E*2 + so, Vh_g + gg);
            cp16(base + 3*TILE_E*2 + so, Vl_g + gg);
        }
    };

    stage_load(0, 0);
    cp_commit();
    {
        __nv_bfloat16* qs = smb + STAGE_E;
        #pragma unroll
        for (int it = 0; it < 4; it++) {
            int id = it * 256 + tid;
            int r = id >> 3, c8 = id & 7;
            size_t gg = (size_t)(b*SEQ + q0 + r) * DIM + h*HDM + c8*8;
            *(uint4*)&qs[r*LDT + c8*8]           = *(const uint4*)&Qh_g[gg];
            *(uint4*)&qs[QT*LDT + r*LDT + c8*8]  = *(const uint4*)&Ql_g[gg];
        }
    }
    __syncthreads();

    uint32_t qh[4][4], ql[4][4];
    {
        uint32_t qb = sb + STAGE_E * 2;
        int rr = warp*16 + (lane & 15);
        int cc = (lane >> 4) * 8;
        #pragma unroll
        for (int kc = 0; kc < 4; kc++) {
            ldsm4(qh[kc], qb + (uint32_t)(rr*LDT + kc*16 + cc) * 2);
            ldsm4(ql[kc], qb + (uint32_t)(QT*LDT + rr*LDT + kc*16 + cc) * 2);
        }
    }

    float oacc[8][4];
    #pragma unroll
    for (int u = 0; u < 8; u++)
        #pragma unroll
        for (int e = 0; e < 4; e++) oacc[u][e] = 0.f;
    float m0 = -1e30f, m1 = -1e30f, l0 = 0.f, l1 = 0.f;

    for (int t = 0; t < SEQ/KT; t++) {
        __syncthreads();
        if (t < SEQ/KT - 1) {
            stage_load((t + 1) & 1, t + 1);
            cp_commit();
            cp_wait1();
        } else {
            cp_wait0();
        }
        __syncthreads();

        uint32_t kb  = sb + (uint32_t)((t & 1) * STAGE_E) * 2;
        uint32_t khb = kb, klb = kb + TILE_E*2;
        uint32_t vhb = kb + 2*TILE_E*2, vlb = kb + 3*TILE_E*2;

        // ---- S = Q K^T (3x comp), prefetched fragments, interleaved accs ----
        float s[8][4];
        #pragma unroll
        for (int j = 0; j < 8; j++)
            #pragma unroll
            for (int e = 0; e < 4; e++) s[j][e] = 0.f;

        {
            uint32_t kfh[2][4], kfl[2][4];
            auto kaddr = [&](int it) -> uint32_t {
                int kc = it >> 2, t2 = it & 3;
                return (uint32_t)(((16*t2 + (lane>>4)*8 + (lane&7)) * LDT
                        + kc*16 + ((lane>>3)&1)*8) * 2);
            };
            ldsm4(kfh[0], khb + kaddr(0));
            ldsm4(kfl[0], klb + kaddr(0));
            #pragma unroll
            for (int it = 0; it < 16; it++) {
                if (it < 15) {
                    ldsm4(kfh[(it+1)&1], khb + kaddr(it+1));
                    ldsm4(kfl[(it+1)&1], klb + kaddr(it+1));
                }
                int kc = it >> 2, t2 = it & 3;
                const uint32_t* kh = kfh[it&1];
                const uint32_t* kl = kfl[it&1];
                mma16816(s[2*t2],   qh[kc], &kh[0], s[2*t2]);
                mma16816(s[2*t2+1], qh[kc], &kh[2], s[2*t2+1]);
                mma16816(s[2*t2],   qh[kc], &kl[0], s[2*t2]);
                mma16816(s[2*t2+1], qh[kc], &kl[2], s[2*t2+1]);
                mma16816(s[2*t2],   ql[kc], &kh[0], s[2*t2]);
                mma16816(s[2*t2+1], ql[kc], &kh[2], s[2*t2+1]);
            }
        }

        // ---- online softmax (base-2 domain; Q was pre-scaled by log2e/8) ----
        float mx0 = -1e30f, mx1 = -1e30f;
        #pragma unroll
        for (int j = 0; j < 8; j++) {
            mx0 = fmaxf(mx0, fmaxf(s[j][0], s[j][1]));
            mx1 = fmaxf(mx1, fmaxf(s[j][2], s[j][3]));
        }
        mx0 = fmaxf(mx0, __shfl_xor_sync(0xffffffffu, mx0, 1));
        mx0 = fmaxf(mx0, __shfl_xor_sync(0xffffffffu, mx0, 2));
        mx1 = fmaxf(mx1, __shfl_xor_sync(0xffffffffu, mx1, 1));
        mx1 = fmaxf(mx1, __shfl_xor_sync(0xffffffffu, mx1, 2));
        float mn0 = fmaxf(m0, mx0), mn1 = fmaxf(m1, mx1);
        float cr0 = fast_exp2(m0 - mn0), cr1 = fast_exp2(m1 - mn1);
        m0 = mn0; m1 = mn1;
        float rs0 = 0.f, rs1 = 0.f;
        #pragma unroll
        for (int j = 0; j < 8; j++) {
            s[j][0] = fast_exp2(s[j][0] - mn0); rs0 += s[j][0];
            s[j][1] = fast_exp2(s[j][1] - mn0); rs0 += s[j][1];
            s[j][2] = fast_exp2(s[j][2] - mn1); rs1 += s[j][2];
            s[j][3] = fast_exp2(s[j][3] - mn1); rs1 += s[j][3];
        }
        l0 = l0 * cr0 + rs0;
        l1 = l1 * cr1 + rs1;
        #pragma unroll
        for (int u = 0; u < 8; u++) {
            oacc[u][0] *= cr0; oacc[u][1] *= cr0;
            oacc[u][2] *= cr1; oacc[u][3] *= cr1;
        }

        // ---- O += P V (3x comp), prefetched V fragments, interleaved accs ----
        {
            uint32_t vfh[2][4], vfl[2][4];
            auto vaddr = [&](int it) -> uint32_t {
                int t2 = it >> 2, u = it & 3;
                return (uint32_t)(((16*t2 + ((lane>>3)&1)*8 + (lane&7)) * LDT
                        + u*16 + (lane>>4)*8) * 2);
            };
            ldsm4t(vfh[0], vhb + vaddr(0));
            ldsm4t(vfl[0], vlb + vaddr(0));
            uint32_t pha[4], pla[4];
            #pragma unroll
            for (int it = 0; it < 16; it++) {
                int t2 = it >> 2, u = it & 3;
                if (u == 0) {
                    split2(s[2*t2][0],   s[2*t2][1],   pha[0], pla[0]);
                    split2(s[2*t2][2],   s[2*t2][3],   pha[1], pla[1]);
                    split2(s[2*t2+1][0], s[2*t2+1][1], pha[2], pla[2]);
                    split2(s[2*t2+1][2], s[2*t2+1][3], pha[3], pla[3]);
                }
                if (it < 15) {
                    ldsm4t(vfh[(it+1)&1], vhb + vaddr(it+1));
                    ldsm4t(vfl[(it+1)&1], vlb + vaddr(it+1));
                }
                const uint32_t* vh = vfh[it&1];
                const uint32_t* vl = vfl[it&1];
                mma16816(oacc[2*u],   pha, &vh[0], oacc[2*u]);
                mma16816(oacc[2*u+1], pha, &vh[2], oacc[2*u+1]);
                mma16816(oacc[2*u],   pha, &vl[0], oacc[2*u]);
                mma16816(oacc[2*u+1], pha, &vl[2], oacc[2*u+1]);
                mma16816(oacc[2*u],   pla, &vh[0], oacc[2*u]);
                mma16816(oacc[2*u+1], pla, &vh[2], oacc[2*u+1]);
            }
        }
    }

    // ---- epilogue: normalize, write bf16 hi/lo ----
    l0 += __shfl_xor_sync(0xffffffffu, l0, 1);
    l0 += __shfl_xor_sync(0xffffffffu, l0, 2);
    l1 += __shfl_xor_sync(0xffffffffu, l1, 1);
    l1 += __shfl_xor_sync(0xffffffffu, l1, 2);
    float inv0 = 1.f / l0, inv1 = 1.f / l1;
    int tok0 = b*SEQ + q0 + warp*16 + (lane >> 2);
    int tok1 = tok0 + 8;
    int colb = h*HDM + (lane & 3) * 2;
    #pragma unroll
    for (int u = 0; u < 8; u++) {
        int col = colb + 8*u;
        uint32_t hh, ll;
        split2(oacc[u][0]*inv0, oacc[u][1]*inv0, hh, ll);
        *(uint32_t*)&Oh_g[(size_t)tok0*DIM + col] = hh;
        *(uint32_t*)&Ol_g[(size_t)tok0*DIM + col] = ll;
        split2(oacc[u][2]*inv1, oacc[u][3]*inv1, hh, ll);
        *(uint32_t*)&Oh_g[(size_t)tok1*DIM + col] = hh;
        *(uint32_t*)&Ol_g[(size_t)tok1*DIM + col] = ll;
    }
}

extern "C" void kernel_launch(void* const* d_in, const int* in_sizes, int n_in,
                              void* d_out, int out_size) {
    const float* query = (const float*)d_in[0];
    const float* key   = (const float*)d_in[1];
    const float* value = (const float*)d_in[2];
    const float* Wq = (const float*)d_in[3];
    const float* bq = (const float*)d_in[4];
    const float* Wk = (const float*)d_in[5];
    const float* bk = (const float*)d_in[6];
    const float* Wv = (const float*)d_in[7];
    const float* bv = (const float*)d_in[8];
    const float* Wo = (const float*)d_in[9];
    const float* bo = (const float*)d_in[10];
    float* out = (float*)d_out;

    __nv_bfloat16 *i0h,*i0l,*i1h,*i1l,*i2h,*i2l;
    __nv_bfloat16 *w0h,*w0l,*w1h,*w1l,*w2h,*w2l,*w3h,*w3l;
    __nv_bfloat16 *qh,*ql,*kh,*kl,*vh,*vl,*ath,*atl;
    cudaGetSymbolAddress((void**)&i0h, g_i0h); cudaGetSymbolAddress((void**)&i0l, g_i0l);
    cudaGetSymbolAddress((void**)&i1h, g_i1h); cudaGetSymbolAddress((void**)&i1l, g_i1l);
    cudaGetSymbolAddress((void**)&i2h, g_i2h); cudaGetSymbolAddress((void**)&i2l, g_i2l);
    cudaGetSymbolAddress((void**)&w0h, g_w0h); cudaGetSymbolAddress((void**)&w0l, g_w0l);
    cudaGetSymbolAddress((void**)&w1h, g_w1h); cudaGetSymbolAddress((void**)&w1l, g_w1l);
    cudaGetSymbolAddress((void**)&w2h, g_w2h); cudaGetSymbolAddress((void**)&w2l, g_w2l);
    cudaGetSymbolAddress((void**)&w3h, g_w3h); cudaGetSymbolAddress((void**)&w3l, g_w3l);
    cudaGetSymbolAddress((void**)&qh,  g_qh);  cudaGetSymbolAddress((void**)&ql,  g_ql);
    cudaGetSymbolAddress((void**)&kh,  g_kh);  cudaGetSymbolAddress((void**)&kl,  g_kl);
    cudaGetSymbolAddress((void**)&vh,  g_vh);  cudaGetSymbolAddress((void**)&vl,  g_vl);
    cudaGetSymbolAddress((void**)&ath, g_ath); cudaGetSymbolAddress((void**)&atl, g_atl);

    cudaFuncSetAttribute(gemm_bf3, cudaFuncAttributeMaxDynamicSharedMemorySize,
                         GEMM_SMEM);
    cudaFuncSetAttribute(flash_mma, cudaFuncAttributeMaxDynamicSharedMemorySize,
                         FLASH_SMEM);

    Split4 sa;
    sa.s[0] = query; sa.h[0] = i0h; sa.l[0] = i0l;
    sa.s[1] = key;   sa.h[1] = i1h; sa.l[1] = i1l;
    sa.s[2] = value; sa.h[2] = i2h; sa.l[2] = i2l;
    sa.s[3] = query; sa.h[3] = i0h; sa.l[3] = i0l;  // unused
    splitk<<<dim3(NTOK*DIM/1024, 1, 3), 256>>>(sa);

    Split4 sw;
    sw.s[0] = Wq; sw.h[0] = w0h; sw.l[0] = w0l;
    sw.s[1] = Wk; sw.h[1] = w1h; sw.l[1] = w1l;
    sw.s[2] = Wv; sw.h[2] = w2h; sw.l[2] = w2l;
    sw.s[3] = Wo; sw.h[3] = w3h; sw.l[3] = w3l;
    splitk<<<dim3(DIM*DIM/1024, 1, 4), 256>>>(sw);

    // QKV projections -> bf16 hi/lo (Q scaled by log2e/8 for base-2 softmax)
    GemmArgs gqkv;
    gqkv.ah[0]=i0h; gqkv.al[0]=i0l; gqkv.wh[0]=w0h; gqkv.wl[0]=w0l; gqkv.bias[0]=bq;
    gqkv.c[0]=nullptr; gqkv.ch[0]=qh; gqkv.cl[0]=ql; gqkv.scale[0]=0.125f*1.44269504f;
    gqkv.ah[1]=i1h; gqkv.al[1]=i1l; gqkv.wh[1]=w1h; gqkv.wl[1]=w1l; gqkv.bias[1]=bk;
    gqkv.c[1]=nullptr; gqkv.ch[1]=kh; gqkv.cl[1]=kl; gqkv.scale[1]=1.f;
    gqkv.ah[2]=i2h; gqkv.al[2]=i2l; gqkv.wh[2]=w2h; gqkv.wl[2]=w2l; gqkv.bias[2]=bv;
    gqkv.c[2]=nullptr; gqkv.ch[2]=vh; gqkv.cl[2]=vl; gqkv.scale[2]=1.f;
    gemm_bf3<<<dim3(DIM/128, NTOK/128, 3), 256, GEMM_SMEM>>>(gqkv);

    flash_mma<<<dim3(SEQ/QT, BTCH*NH), 256, FLASH_SMEM>>>(qh, ql, kh, kl, vh, vl,
                                                          ath, atl);

    GemmArgs go;
    go.ah[0]=ath; go.al[0]=atl; go.wh[0]=w3h; go.wl[0]=w3l; go.bias[0]=bo;
    go.c[0]=out; go.ch[0]=nullptr; go.cl[0]=nullptr; go.scale[0]=1.f;
    go.ah[1]=ath; go.al[1]=atl; go.wh[1]=w3h; go.wl[1]=w3l; go.bias[1]=bo;
    go.c[1]=out; go.ch[1]=nullptr; go.cl[1]=nullptr; go.scale[1]=1.f;
    go.ah[2]=ath; go.al[2]=atl; go.wh[2]=w3h; go.wl[2]=w3l; go.bias[2]=bo;
    go.c[2]=out; go.ch[2]=nullptr; go.cl[2]=nullptr; go.scale[2]=1.f;
    gemm_bf3<<<dim3(DIM/128, NTOK/128, 1), 256, GEMM_SMEM>>>(go);
}

// round 17
// speedup vs baseline: 1.2543x; 1.2543x over previous
#include <cuda_runtime.h>
#include <cuda_bf16.h>
#include <cstdint>
#include <math.h>

#define BTCH 2
#define SEQ  2048
#define DIM  1024
#define NH   16
#define HDM  64
#define NTOK (BTCH*SEQ)

// ---------------- device global scratch (no allocs allowed) ----------------
__device__ __nv_bfloat16 g_i0h[NTOK*DIM], g_i0l[NTOK*DIM];
__device__ __nv_bfloat16 g_i1h[NTOK*DIM], g_i1l[NTOK*DIM];
__device__ __nv_bfloat16 g_i2h[NTOK*DIM], g_i2l[NTOK*DIM];
__device__ __nv_bfloat16 g_w0h[DIM*DIM], g_w0l[DIM*DIM];
__device__ __nv_bfloat16 g_w1h[DIM*DIM], g_w1l[DIM*DIM];
__device__ __nv_bfloat16 g_w2h[DIM*DIM], g_w2l[DIM*DIM];
__device__ __nv_bfloat16 g_w3h[DIM*DIM], g_w3l[DIM*DIM];
__device__ __nv_bfloat16 g_qh[NTOK*DIM], g_ql[NTOK*DIM];
__device__ __nv_bfloat16 g_kh[NTOK*DIM], g_kl[NTOK*DIM];
__device__ __nv_bfloat16 g_vh[NTOK*DIM], g_vl[NTOK*DIM];
__device__ __nv_bfloat16 g_ath[NTOK*DIM], g_atl[NTOK*DIM];

__device__ __forceinline__ uint2 pack4_bf16(float a, float b, float c, float d) {
    __nv_bfloat162 lo = __floats2bfloat162_rn(a, b);
    __nv_bfloat162 hi = __floats2bfloat162_rn(c, d);
    uint2 r;
    r.x = *reinterpret_cast<uint32_t*>(&lo);
    r.y = *reinterpret_cast<uint32_t*>(&hi);
    return r;
}

// FMA-pipe exp: exp(x) for x <= 0. ~1e-7 abs accuracy.
__device__ __forceinline__ float fast_exp(float x) {
    x = fmaxf(x, -80.f);
    float t = x * 1.4426950408889634f;
    float z = t + 12582912.f;
    float fn = z - 12582912.f;
    float f = t - fn;
    int n = __float_as_int(z);
    float p = 0.0013333558f;
    p = fmaf(p, f, 0.0096181291f);
    p = fmaf(p, f, 0.0555041087f);
    p = fmaf(p, f, 0.2402264923f);
    p = fmaf(p, f, 0.6931471806f);
    p = fmaf(p, f, 1.0f);
    return __int_as_float(__float_as_int(p) + (n << 23));
}

__device__ __forceinline__ void cp16(uint32_t dst, const void* src) {
    asm volatile("cp.async.cg.shared.global [%0], [%1], 16;"
                 :: "r"(dst), "l"(src) : "memory");
}
__device__ __forceinline__ void cp_commit() {
    asm volatile("cp.async.commit_group;" ::: "memory");
}
__device__ __forceinline__ void cp_wait1() {
    asm volatile("cp.async.wait_group 1;" ::: "memory");
}
__device__ __forceinline__ void cp_wait0() {
    asm volatile("cp.async.wait_group 0;" ::: "memory");
}

__device__ __forceinline__ void mma16816(float* d, const uint32_t* a,
                                         const uint32_t* b, const float* c) {
    asm volatile("mma.sync.aligned.m16n8k16.row.col.f32.bf16.bf16.f32 "
        "{%0,%1,%2,%3}, {%4,%5,%6,%7}, {%8,%9}, {%10,%11,%12,%13};"
        : "=f"(d[0]),"=f"(d[1]),"=f"(d[2]),"=f"(d[3])
        : "r"(a[0]),"r"(a[1]),"r"(a[2]),"r"(a[3]), "r"(b[0]),"r"(b[1]),
          "f"(c[0]),"f"(c[1]),"f"(c[2]),"f"(c[3]));
}
__device__ __forceinline__ void ldsm4(uint32_t* r, uint32_t addr) {
    asm volatile("ldmatrix.sync.aligned.m8n8.x4.shared.b16 {%0,%1,%2,%3}, [%4];"
        : "=r"(r[0]),"=r"(r[1]),"=r"(r[2]),"=r"(r[3]) : "r"(addr));
}
__device__ __forceinline__ void ldsm4t(uint32_t* r, uint32_t addr) {
    asm volatile("ldmatrix.sync.aligned.m8n8.x4.trans.shared.b16 {%0,%1,%2,%3}, [%4];"
        : "=r"(r[0]),"=r"(r[1]),"=r"(r[2]),"=r"(r[3]) : "r"(addr));
}
__device__ __forceinline__ void split2(float x, float y, uint32_t& h, uint32_t& l) {
    __nv_bfloat162 hh = __floats2bfloat162_rn(x, y);
    float hx = __bfloat162float(hh.x), hy = __bfloat162float(hh.y);
    __nv_bfloat162 ll = __floats2bfloat162_rn(x - hx, y - hy);
    h = *reinterpret_cast<uint32_t*>(&hh);
    l = *reinterpret_cast<uint32_t*>(&ll);
}

// ---------------------------------------------------------------------------
// fp32 -> bf16 hi/lo split (activations + weights)
// ---------------------------------------------------------------------------
struct Split4 {
    const float* s[4];
    __nv_bfloat16* h[4];
    __nv_bfloat16* l[4];
};
__global__ void splitk(Split4 a) {
    int z = blockIdx.z;
    size_t i = ((size_t)blockIdx.x * blockDim.x + threadIdx.x) * 4;
    float4 v = *(const float4*)(a.s[z] + i);
    float hx = __bfloat162float(__float2bfloat16(v.x));
    float hy = __bfloat162float(__float2bfloat16(v.y));
    float hz = __bfloat162float(__float2bfloat16(v.z));
    float hw = __bfloat162float(__float2bfloat16(v.w));
    *(uint2*)(a.h[z] + i) = pack4_bf16(hx, hy, hz, hw);
    *(uint2*)(a.l[z] + i) = pack4_bf16(v.x - hx, v.y - hy, v.z - hz, v.w - hw);
}

// ---------------------------------------------------------------------------
// gemm_v2: raw mma.sync bf16 GEMM + bias, 3x comp.
// XOR-swizzled smem (no padding), 3-stage cp.async ring, ONE sync per chunk.
// CTA 128x128, K-chunk 32, 8 warps (4M x 2N), warp tile 32x64.
// Stage layout (32KB): Ah[128x64B] | Al | Bh[32x256B] | Bl  (8KB each)
// ---------------------------------------------------------------------------
struct GemmArgs {
    const __nv_bfloat16 *ah[3], *al[3], *wh[3], *wl[3];
    const float* bias[3];
    float* c[3];
    __nv_bfloat16 *ch[3], *cl[3];
    float scale[3];
};

#define GSTAGE 32768
#define GEMM_SMEM (3*GSTAGE)

__global__ __launch_bounds__(256, 2)
void gemm_v2(GemmArgs g) {
    extern __shared__ __align__(16) char sm[];
    int z = blockIdx.z;
    const __nv_bfloat16* Ahg = g.ah[z];
    const __nv_bfloat16* Alg = g.al[z];
    const __nv_bfloat16* Whg = g.wh[z];
    const __nv_bfloat16* Wlg = g.wl[z];

    int tid  = threadIdx.x;
    int warp = tid >> 5;
    int lane = tid & 31;
    int wm   = warp >> 1;          // 0..3 (M 32-tiles)
    int wn   = warp & 1;           // 0..1 (N 64-halves)
    int m0 = blockIdx.y * 128;
    int n0 = blockIdx.x * 128;

    uint32_t sbase = (uint32_t)__cvta_generic_to_shared(sm);

    auto stage_load = [&](int st, int c) {
        uint32_t base = sbase + st * GSTAGE;
        #pragma unroll
        for (int it = 0; it < 2; it++) {
            int idx = it * 256 + tid;          // 0..511
            int row = idx >> 2, c4 = idx & 3;  // A: 128 rows x 4 16B-chunks
            uint32_t dst = base + row * 64 + (uint32_t)((c4 ^ ((row >> 1) & 3)) * 16);
            size_t so = (size_t)(m0 + row) * DIM + c * 32 + c4 * 8;
            cp16(dst, Ahg + so);
            cp16(dst + 8192, Alg + so);
        }
        #pragma unroll
        for (int it = 0; it < 2; it++) {
            int idx = it * 256 + tid;
            int row = idx >> 4, c16 = idx & 15; // B: 32 k-rows x 16 16B-chunks
            uint32_t dst = base + 16384 + row * 256 + (uint32_t)((c16 ^ (row & 7)) * 16);
            size_t so = (size_t)(c * 32 + row) * DIM + n0 + c16 * 8;
            cp16(dst, Whg + so);
            cp16(dst + 8192, Wlg + so);
        }
    };

    float acc[2][8][4];
    #pragma unroll
    for (int mi = 0; mi < 2; mi++)
        #pragma unroll
        for (int j = 0; j < 8; j++)
            #pragma unroll
            for (int e = 0; e < 4; e++) acc[mi][j][e] = 0.f;

    stage_load(0, 0); cp_commit();
    stage_load(1, 1); cp_commit();

    for (int c = 0; c < 32; c++) {
        if (c >= 30) cp_wait0(); else cp_wait1();
        __syncthreads();
        if (c < 30) { stage_load((c + 2) % 3, c + 2); cp_commit(); }

        uint32_t Ab = sbase + (uint32_t)((c % 3) * GSTAGE);
        uint32_t Bb = Ab + 16384;

        #pragma unroll
        for (int kk = 0; kk < 2; kk++) {
            uint32_t ah[2][4], al[2][4];
            #pragma unroll
            for (int mi = 0; mi < 2; mi++) {
                int row = wm * 32 + mi * 16 + (lane & 15);
                int ch  = kk * 2 + (lane >> 4);
                uint32_t ad = Ab + row * 64 + (uint32_t)((ch ^ ((row >> 1) & 3)) * 16);
                ldsm4(ah[mi], ad);
                ldsm4(al[mi], ad + 8192);
            }
            #pragma unroll
            for (int nj = 0; nj < 4; nj++) {
                int krow = kk * 16 + ((lane >> 3) & 1) * 8 + (lane & 7);
                int ch   = wn * 8 + nj * 2 + (lane >> 4);
                uint32_t bd = Bb + krow * 256 + (uint32_t)((ch ^ (krow & 7)) * 16);
                uint32_t bh[4], bl[4];
                ldsm4t(bh, bd);
                ldsm4t(bl, bd + 8192);
                mma16816(acc[0][2*nj],   ah[0], &bh[0], acc[0][2*nj]);
                mma16816(acc[1][2*nj],   ah[1], &bh[0], acc[1][2*nj]);
                mma16816(acc[0][2*nj+1], ah[0], &bh[2], acc[0][2*nj+1]);
                mma16816(acc[1][2*nj+1], ah[1], &bh[2], acc[1][2*nj+1]);
                mma16816(acc[0][2*nj],   ah[0], &bl[0], acc[0][2*nj]);
                mma16816(acc[1][2*nj],   ah[1], &bl[0], acc[1][2*nj]);
                mma16816(acc[0][2*nj+1], ah[0], &bl[2], acc[0][2*nj+1]);
                mma16816(acc[1][2*nj+1], ah[1], &bl[2], acc[1][2*nj+1]);
                mma16816(acc[0][2*nj],   al[0], &bh[0], acc[0][2*nj]);
                mma16816(acc[1][2*nj],   al[1], &bh[0], acc[1][2*nj]);
                mma16816(acc[0][2*nj+1], al[0], &bh[2], acc[0][2*nj+1]);
                mma16816(acc[1][2*nj+1], al[1], &bh[2], acc[1][2*nj+1]);
            }
        }
    }

    // ---- epilogue: bias add + store (fp32 or scaled bf16 hi/lo) ----
    const float* bias = g.bias[z];
    int cb = n0 + wn * 64 + (lane & 3) * 2;
    if (g.ch[z]) {
        __nv_bfloat16* CH = g.ch[z];
        __nv_bfloat16* CL = g.cl[z];
        float sc = g.scale[z];
        #pragma unroll
        for (int mi = 0; mi < 2; mi++) {
            int r0 = m0 + wm * 32 + mi * 16 + (lane >> 2);
            #pragma unroll
            for (int j = 0; j < 8; j++) {
                int col = cb + j * 8;
                float b0 = bias[col], b1 = bias[col + 1];
                uint32_t hh, ll;
                split2((acc[mi][j][0] + b0) * sc, (acc[mi][j][1] + b1) * sc, hh, ll);
                *(uint32_t*)&CH[(size_t)r0 * DIM + col] = hh;
                *(uint32_t*)&CL[(size_t)r0 * DIM + col] = ll;
                split2((acc[mi][j][2] + b0) * sc, (acc[mi][j][3] + b1) * sc, hh, ll);
                *(uint32_t*)&CH[(size_t)(r0 + 8) * DIM + col] = hh;
                *(uint32_t*)&CL[(size_t)(r0 + 8) * DIM + col] = ll;
            }
        }
    } else {
        float* C = g.c[z];
        #pragma unroll
        for (int mi = 0; mi < 2; mi++) {
            int r0 = m0 + wm * 32 + mi * 16 + (lane >> 2);
            #pragma unroll
            for (int j = 0; j < 8; j++) {
                int col = cb + j * 8;
                float b0 = bias[col], b1 = bias[col + 1];
                *(float2*)&C[(size_t)r0 * DIM + col] =
                    make_float2(acc[mi][j][0] + b0, acc[mi][j][1] + b1);
                *(float2*)&C[(size_t)(r0 + 8) * DIM + col] =
                    make_float2(acc[mi][j][2] + b0, acc[mi][j][3] + b1);
            }
        }
    }
}

// ---------------------------------------------------------------------------
// FlashAttention-2 style mma.sync bf16 flash (R13 version, verbatim).
// ---------------------------------------------------------------------------
#define QT 128
#define KT 64
#define LDT 72
#define TILE_E (KT*LDT)
#define STAGE_E (4*TILE_E)
#define FLASH_SMEM (2*STAGE_E*2)

__global__ __launch_bounds__(256, 2)
void flash_mma(const __nv_bfloat16* __restrict__ Qh_g, const __nv_bfloat16* __restrict__ Ql_g,
               const __nv_bfloat16* __restrict__ Kh_g, const __nv_bfloat16* __restrict__ Kl_g,
               const __nv_bfloat16* __restrict__ Vh_g, const __nv_bfloat16* __restrict__ Vl_g,
               __nv_bfloat16* __restrict__ Oh_g, __nv_bfloat16* __restrict__ Ol_g) {
    extern __shared__ __align__(16) char sm[];
    __nv_bfloat16* smb = (__nv_bfloat16*)sm;
    uint32_t sb = (uint32_t)__cvta_generic_to_shared(sm);

    int tid = threadIdx.x, lane = tid & 31, warp = tid >> 5;
    int bh = blockIdx.y, b = bh >> 4, h = bh & 15;
    int q0 = blockIdx.x * QT;

    auto stage_load = [&](int st, int t) {
        uint32_t base = sb + st * STAGE_E * 2;
        #pragma unroll
        for (int it2 = 0; it2 < 2; it2++) {
            int rem = it2 * 256 + tid;
            int r = rem >> 3, c8 = rem & 7;
            size_t gg = (size_t)(b*SEQ + t*KT + r) * DIM + h*HDM + c8*8;
            uint32_t so = (uint32_t)(r*LDT + c8*8) * 2;
            cp16(base + 0*TILE_E*2 + so, Kh_g + gg);
            cp16(base + 1*TILE_E*2 + so, Kl_g + gg);
            cp16(base + 2*TILE_E*2 + so, Vh_g + gg);
            cp16(base + 3*TILE_E*2 + so, Vl_g + gg);
        }
    };

    stage_load(0, 0);
    cp_commit();
    {
        __nv_bfloat16* qs = smb + STAGE_E;
        #pragma unroll
        for (int it = 0; it < 4; it++) {
            int id = it * 256 + tid;
            int r = id >> 3, c8 = id & 7;
            size_t gg = (size_t)(b*SEQ + q0 + r) * DIM + h*HDM + c8*8;
            *(uint4*)&qs[r*LDT + c8*8]           = *(const uint4*)&Qh_g[gg];
            *(uint4*)&qs[QT*LDT + r*LDT + c8*8]  = *(const uint4*)&Ql_g[gg];
        }
    }
    __syncthreads();

    uint32_t qh[4][4], ql[4][4];
    {
        uint32_t qb = sb + STAGE_E * 2;
        int rr = warp*16 + (lane & 15);
        int cc = (lane >> 4) * 8;
        #pragma unroll
        for (int kc = 0; kc < 4; kc++) {
            ldsm4(qh[kc], qb + (uint32_t)(rr*LDT + kc*16 + cc) * 2);
            ldsm4(ql[kc], qb + (uint32_t)(QT*LDT + rr*LDT + kc*16 + cc) * 2);
        }
    }

    float oacc[8][4];
    #pragma unroll
    for (int u = 0; u < 8; u++)
        #pragma unroll
        for (int e = 0; e < 4; e++) oacc[u][e] = 0.f;
    float m0 = -1e30f, m1 = -1e30f, l0 = 0.f, l1 = 0.f;

    for (int t = 0; t < SEQ/KT; t++) {
        __syncthreads();
        if (t < SEQ/KT - 1) {
            stage_load((t + 1) & 1, t + 1);
            cp_commit();
            cp_wait1();
        } else {
            cp_wait0();
        }
        __syncthreads();

        uint32_t kb  = sb + (uint32_t)((t & 1) * STAGE_E) * 2;
        uint32_t khb = kb, klb = kb + TILE_E*2;
        uint32_t vhb = kb + 2*TILE_E*2, vlb = kb + 3*TILE_E*2;

        float s[8][4];
        #pragma unroll
        for (int j = 0; j < 8; j++)
            #pragma unroll
            for (int e = 0; e < 4; e++) s[j][e] = 0.f;

        #pragma unroll
        for (int kc = 0; kc < 4; kc++) {
            #pragma unroll
            for (int t2 = 0; t2 < 4; t2++) {
                uint32_t kh[4], kl[4];
                uint32_t ka = (uint32_t)(((16*t2 + (lane>>4)*8 + (lane&7)) * LDT
                              + kc*16 + ((lane>>3)&1)*8) * 2);
                ldsm4(kh, khb + ka);
                ldsm4(kl, klb + ka);
                mma16816(s[2*t2],   qh[kc], &kh[0], s[2*t2]);
                mma16816(s[2*t2],   qh[kc], &kl[0], s[2*t2]);
                mma16816(s[2*t2],   ql[kc], &kh[0], s[2*t2]);
                mma16816(s[2*t2+1], qh[kc], &kh[2], s[2*t2+1]);
                mma16816(s[2*t2+1], qh[kc], &kl[2], s[2*t2+1]);
                mma16816(s[2*t2+1], ql[kc], &kh[2], s[2*t2+1]);
            }
        }

        float mx0 = -1e30f, mx1 = -1e30f;
        #pragma unroll
        for (int j = 0; j < 8; j++) {
            mx0 = fmaxf(mx0, fmaxf(s[j][0], s[j][1]));
            mx1 = fmaxf(mx1, fmaxf(s[j][2], s[j][3]));
        }
        mx0 = fmaxf(mx0, __shfl_xor_sync(0xffffffffu, mx0, 1));
        mx0 = fmaxf(mx0, __shfl_xor_sync(0xffffffffu, mx0, 2));
        mx1 = fmaxf(mx1, __shfl_xor_sync(0xffffffffu, mx1, 1));
        mx1 = fmaxf(mx1, __shfl_xor_sync(0xffffffffu, mx1, 2));
        float mn0 = fmaxf(m0, mx0), mn1 = fmaxf(m1, mx1);
        float cr0 = fast_exp(m0 - mn0), cr1 = fast_exp(m1 - mn1);
        m0 = mn0; m1 = mn1;
        float rs0 = 0.f, rs1 = 0.f;
        #pragma unroll
        for (int j = 0; j < 8; j++) {
            s[j][0] = fast_exp(s[j][0] - mn0); rs0 += s[j][0];
            s[j][1] = fast_exp(s[j][1] - mn0); rs0 += s[j][1];
            s[j][2] = fast_exp(s[j][2] - mn1); rs1 += s[j][2];
            s[j][3] = fast_exp(s[j][3] - mn1); rs1 += s[j][3];
        }
        l0 = l0 * cr0 + rs0;
        l1 = l1 * cr1 + rs1;
        #pragma unroll
        for (int u = 0; u < 8; u++) {
            oacc[u][0] *= cr0; oacc[u][1] *= cr0;
            oacc[u][2] *= cr1; oacc[u][3] *= cr1;
        }

        #pragma unroll
        for (int t2 = 0; t2 < 4; t2++) {
            uint32_t pha[4], pla[4];
            split2(s[2*t2][0],   s[2*t2][1],   pha[0], pla[0]);
            split2(s[2*t2][2],   s[2*t2][3],   pha[1], pla[1]);
            split2(s[2*t2+1][0], s[2*t2+1][1], pha[2], pla[2]);
            split2(s[2*t2+1][2], s[2*t2+1][3], pha[3], pla[3]);
            #pragma unroll
            for (int u = 0; u < 4; u++) {
                uint32_t vh[4], vl[4];
                uint32_t va = (uint32_t)(((16*t2 + ((lane>>3)&1)*8 + (lane&7)) * LDT
                              + u*16 + (lane>>4)*8) * 2);
                ldsm4t(vh, vhb + va);
                ldsm4t(vl, vlb + va);
                mma16816(oacc[2*u],   pha, &vh[0], oacc[2*u]);
                mma16816(oacc[2*u],   pha, &vl[0], oacc[2*u]);
                mma16816(oacc[2*u],   pla, &vh[0], oacc[2*u]);
                mma16816(oacc[2*u+1], pha, &vh[2], oacc[2*u+1]);
                mma16816(oacc[2*u+1], pha, &vl[2], oacc[2*u+1]);
                mma16816(oacc[2*u+1], pla, &vh[2], oacc[2*u+1]);
            }
        }
    }

    l0 += __shfl_xor_sync(0xffffffffu, l0, 1);
    l0 += __shfl_xor_sync(0xffffffffu, l0, 2);
    l1 += __shfl_xor_sync(0xffffffffu, l1, 1);
    l1 += __shfl_xor_sync(0xffffffffu, l1, 2);
    float inv0 = 1.f / l0, inv1 = 1.f / l1;
    int tok0 = b*SEQ + q0 + warp*16 + (lane >> 2);
    int tok1 = tok0 + 8;
    int colb = h*HDM + (lane & 3) * 2;
    #pragma unroll
    for (int u = 0; u < 8; u++) {
        int col = colb + 8*u;
        uint32_t hh, ll;
        split2(oacc[u][0]*inv0, oacc[u][1]*inv0, hh, ll);
        *(uint32_t*)&Oh_g[(size_t)tok0*DIM + col] = hh;
        *(uint32_t*)&Ol_g[(size_t)tok0*DIM + col] = ll;
        split2(oacc[u][2]*inv1, oacc[u][3]*inv1, hh, ll);
        *(uint32_t*)&Oh_g[(size_t)tok1*DIM + col] = hh;
        *(uint32_t*)&Ol_g[(size_t)tok1*DIM + col] = ll;
    }
}

extern "C" void kernel_launch(void* const* d_in, const int* in_sizes, int n_in,
                              void* d_out, int out_size) {
    const float* query = (const float*)d_in[0];
    const float* key   = (const float*)d_in[1];
    const float* value = (const float*)d_in[2];
    const float* Wq = (const float*)d_in[3];
    const float* bq = (const float*)d_in[4];
    const float* Wk = (const float*)d_in[5];
    const float* bk = (const float*)d_in[6];
    const float* Wv = (const float*)d_in[7];
    const float* bv = (const float*)d_in[8];
    const float* Wo = (const float*)d_in[9];
    const float* bo = (const float*)d_in[10];
    float* out = (float*)d_out;

    __nv_bfloat16 *i0h,*i0l,*i1h,*i1l,*i2h,*i2l;
    __nv_bfloat16 *w0h,*w0l,*w1h,*w1l,*w2h,*w2l,*w3h,*w3l;
    __nv_bfloat16 *qh,*ql,*kh,*kl,*vh,*vl,*ath,*atl;
    cudaGetSymbolAddress((void**)&i0h, g_i0h); cudaGetSymbolAddress((void**)&i0l, g_i0l);
    cudaGetSymbolAddress((void**)&i1h, g_i1h); cudaGetSymbolAddress((void**)&i1l, g_i1l);
    cudaGetSymbolAddress((void**)&i2h, g_i2h); cudaGetSymbolAddress((void**)&i2l, g_i2l);
    cudaGetSymbolAddress((void**)&w0h, g_w0h); cudaGetSymbolAddress((void**)&w0l, g_w0l);
    cudaGetSymbolAddress((void**)&w1h, g_w1h); cudaGetSymbolAddress((void**)&w1l, g_w1l);
    cudaGetSymbolAddress((void**)&w2h, g_w2h); cudaGetSymbolAddress((void**)&w2l, g_w2l);
    cudaGetSymbolAddress((void**)&w3h, g_w3h); cudaGetSymbolAddress((void**)&w3l, g_w3l);
    cudaGetSymbolAddress((void**)&qh,  g_qh);  cudaGetSymbolAddress((void**)&ql,  g_ql);
    cudaGetSymbolAddress((void**)&kh,  g_kh);  cudaGetSymbolAddress((void**)&kl,  g_kl);
    cudaGetSymbolAddress((void**)&vh,  g_vh);  cudaGetSymbolAddress((void**)&vl,  g_vl);
    cudaGetSymbolAddress((void**)&ath, g_ath); cudaGetSymbolAddress((void**)&atl, g_atl);

    cudaFuncSetAttribute(gemm_v2, cudaFuncAttributeMaxDynamicSharedMemorySize,
                         GEMM_SMEM);
    cudaFuncSetAttribute(flash_mma, cudaFuncAttributeMaxDynamicSharedMemorySize,
                         FLASH_SMEM);

    Split4 sa;
    sa.s[0] = query; sa.h[0] = i0h; sa.l[0] = i0l;
    sa.s[1] = key;   sa.h[1] = i1h; sa.l[1] = i1l;
    sa.s[2] = value; sa.h[2] = i2h; sa.l[2] = i2l;
    sa.s[3] = query; sa.h[3] = i0h; sa.l[3] = i0l;  // unused
    splitk<<<dim3(NTOK*DIM/1024, 1, 3), 256>>>(sa);

    Split4 sw;
    sw.s[0] = Wq; sw.h[0] = w0h; sw.l[0] = w0l;
    sw.s[1] = Wk; sw.h[1] = w1h; sw.l[1] = w1l;
    sw.s[2] = Wv; sw.h[2] = w2h; sw.l[2] = w2l;
    sw.s[3] = Wo; sw.h[3] = w3h; sw.l[3] = w3l;
    splitk<<<dim3(DIM*DIM/1024, 1, 4), 256>>>(sw);

    // QKV projections -> bf16 hi/lo (Q scaled by 1/8, exact)
    GemmArgs gqkv;
    gqkv.ah[0]=i0h; gqkv.al[0]=i0l; gqkv.wh[0]=w0h; gqkv.wl[0]=w0l; gqkv.bias[0]=bq;
    gqkv.c[0]=nullptr; gqkv.ch[0]=qh; gqkv.cl[0]=ql; gqkv.scale[0]=0.125f;
    gqkv.ah[1]=i1h; gqkv.al[1]=i1l; gqkv.wh[1]=w1h; gqkv.wl[1]=w1l; gqkv.bias[1]=bk;
    gqkv.c[1]=nullptr; gqkv.ch[1]=kh; gqkv.cl[1]=kl; gqkv.scale[1]=1.f;
    gqkv.ah[2]=i2h; gqkv.al[2]=i2l; gqkv.wh[2]=w2h; gqkv.wl[2]=w2l; gqkv.bias[2]=bv;
    gqkv.c[2]=nullptr; gqkv.ch[2]=vh; gqkv.cl[2]=vl; gqkv.scale[2]=1.f;
    gemm_v2<<<dim3(DIM/128, NTOK/128, 3), 256, GEMM_SMEM>>>(gqkv);

    flash_mma<<<dim3(SEQ/QT, BTCH*NH), 256, FLASH_SMEM>>>(qh, ql, kh, kl, vh, vl,
                                                          ath, atl);

    GemmArgs go;
    go.ah[0]=ath; go.al[0]=atl; go.wh[0]=w3h; go.wl[0]=w3l; go.bias[0]=bo;
    go.c[0]=out; go.ch[0]=nullptr; go.cl[0]=nullptr; go.scale[0]=1.f;
    go.ah[1]=ath; go.al[1]=atl; go.wh[1]=w3h; go.wl[1]=w3l; go.bias[1]=bo;
    go.c[1]=out; go.ch[1]=nullptr; go.cl[1]=nullptr; go.scale[1]=1.f;
    go.ah[2]=ath; go.al[2]=atl; go.wh[2]=w3h; go.wl[2]=w3l; go.bias[2]=bo;
    go.c[2]=out; go.ch[2]=nullptr; go.cl[2]=nullptr; go.scale[2]=1.f;
    gemm_v2<<<dim3(DIM/128, NTOK/128, 1), 256, GEMM_SMEM>>>(go);
}